// round 15
// baseline (speedup 1.0000x reference)
#include <cuda_runtime.h>
#include <math.h>

#define NN    512
#define HH    1024
#define EE    16384
#define LINK  (NN*HH)     // 524288
#define CELLS (NN*NN)     // 262144
#define OSPLIT 64
#define OCHUNK (LINK/OSPLIT)   // 8192 floats = 32 KB
#define ZHX   64               // k_hx split-K chunks

// ---------------- scratch (device globals; no allocation allowed) -------------
__device__ __align__(16) float g_P[ZHX][128*1024]; // k_hx split-K partials (32 MB)
__device__ __align__(16) float g_Q[4][LINK];       // k_hp split-K partials (8 MB)
__device__ __align__(16) float g_PI[32][4*1024];   // k_himg split-K partials
__device__ __align__(16) float g_hImg[4*1024];     // img contribution (4x1024)
__device__ __align__(16) float g_h[LINK];          // h (512x1024)
__device__ __align__(16) float g_Wa1[4096];        // W @ a[0:1024]
__device__ __align__(16) float g_Wa2[4096];        // W @ a[1024:2048]
__device__ float g_ha1[NN];
__device__ float g_ha2[NN];
__device__ int   g_win[CELLS];
__device__ __align__(16) float g_e[CELLS];
__device__ __align__(16) float g_adj[CELLS];
__device__ __align__(16) float g_att[CELLS];
__device__ __align__(16) float g_hp[LINK];         // h_prime (512x1024)
__device__ float g_part[OSPLIT*513];
__device__ float g_mn[128], g_mx[128];
__device__ float g_amin_f, g_amax_f;

// ---------------- zero / init -------------------------------------------------
__global__ void k_zero() {
    int i = blockIdx.x * 1024 + threadIdx.x;       // grid 256 x 1024 = 262144
    g_win[i] = -1;                                 // last-wins sentinel
    g_e[i]   = 0.0f;
    g_adj[i] = 0.0f;
}

// ---------------- Wa1[j] = sum_c W[j,c] a[c] ; Wa2[j] = sum_c W[j,c] a[1024+c]
__global__ void k_wa(const float* __restrict__ W, const float* __restrict__ a) {
    int j = blockIdx.x;                            // 4096 blocks x 128 threads
    int t = threadIdx.x;
    float s1 = 0.f, s2 = 0.f;
    for (int c = t; c < 1024; c += 128) {
        float w = W[(size_t)j * 1024 + c];
        s1 += w * a[c];
        s2 += w * a[1024 + c];
    }
    __shared__ float r1[128], r2[128];
    r1[t] = s1; r2[t] = s2;
    __syncthreads();
    for (int off = 64; off > 0; off >>= 1) {
        if (t < off) { r1[t] += r1[t + off]; r2[t] += r2[t + off]; }
        __syncthreads();
    }
    if (t == 0) { g_Wa1[j] = r1[0]; g_Wa2[j] = r2[0]; }
}

// ---------------- ha1[i] = sum_j fx[i,j] Wa1[j] (fx computed inline) ----------
__global__ void k_havec(const float* __restrict__ X, const float* __restrict__ img) {
    int i = blockIdx.x;                            // 512 blocks x 256 threads
    int t = threadIdx.x;
    int base_n = 4 * (i & 127);
    int b = i >> 7;
    float s1 = 0.f, s2 = 0.f;
    for (int j = t; j < 4096; j += 256) {
        int hh = j & 1023;
        float fx = X[(size_t)(base_n + (j >> 10)) * 1024 + hh]
                 + img[(size_t)b * 1024 + hh];
        s1 += fx * g_Wa1[j];
        s2 += fx * g_Wa2[j];
    }
    __shared__ float r1[256], r2[256];
    r1[t] = s1; r2[t] = s2;
    __syncthreads();
    for (int off = 128; off > 0; off >>= 1) {
        if (t < off) { r1[t] += r1[t + off]; r2[t] += r2[t + off]; }
        __syncthreads();
    }
    if (t == 0) { g_ha1[i] = r1[0]; g_ha2[i] = r2[0]; }
}

// ---------------- core GEMM: smem X tile + float4 W loads --------------------
// z in [0,64): q = z>>4, hh0 = (z&15)*64. grid (16 m-groups, 64 z), 256 thr.
__global__ void __launch_bounds__(256, 3) k_hx(const float* __restrict__ X,
                                               const float* __restrict__ W) {
    __shared__ float Xs[8][64];
    int t = threadIdx.x;
    int m0 = blockIdx.x * 8;
    int z  = blockIdx.y;
    int q = z >> 4, hh0 = (z & 15) * 64;

    if (t < 128) {  // X tile: rows 4*(m0+i)+q, cols hh0..hh0+63 (8x16 float4)
        int i = t >> 4, f4 = t & 15;
        float4 xv = *(const float4*)(X + (size_t)(4 * (m0 + i) + q) * 1024 + hh0 + f4 * 4);
        *(float4*)&Xs[i][f4 * 4] = xv;
    }
    __syncthreads();

    const float* Wb = W + (size_t)(q * 1024 + hh0) * 1024 + t * 4;
    float acc[8][4];
#pragma unroll
    for (int i = 0; i < 8; i++)
#pragma unroll
        for (int j = 0; j < 4; j++) acc[i][j] = 0.f;

    for (int hh = 0; hh < 64; hh += 4) {
        float4 w0 = *(const float4*)(Wb + (size_t)(hh + 0) * 1024);
        float4 w1 = *(const float4*)(Wb + (size_t)(hh + 1) * 1024);
        float4 w2 = *(const float4*)(Wb + (size_t)(hh + 2) * 1024);
        float4 w3 = *(const float4*)(Wb + (size_t)(hh + 3) * 1024);
#pragma unroll
        for (int i = 0; i < 8; i++) {
            float4 x = *(const float4*)&Xs[i][hh];
            acc[i][0] += x.x * w0.x + x.y * w1.x + x.z * w2.x + x.w * w3.x;
            acc[i][1] += x.x * w0.y + x.y * w1.y + x.z * w2.y + x.w * w3.y;
            acc[i][2] += x.x * w0.z + x.y * w1.z + x.z * w2.z + x.w * w3.z;
            acc[i][3] += x.x * w0.w + x.y * w1.w + x.z * w2.w + x.w * w3.w;
        }
    }
#pragma unroll
    for (int i = 0; i < 8; i++)
        *(float4*)&g_P[z][(size_t)(m0 + i) * 1024 + t * 4] =
            make_float4(acc[i][0], acc[i][1], acc[i][2], acc[i][3]);
}

// ---------------- img @ W (grid 16 x 32) -------------------------------------
__global__ void k_himg(const float* __restrict__ img, const float* __restrict__ W) {
    int t = threadIdx.x;
    int lane = t & 63, s = t >> 6;
    int c = blockIdx.x * 64 + lane;
    int z = blockIdx.y;                             // 32 chunks of 32 hh
    float acc[4] = {0.f,0.f,0.f,0.f};
    for (int hh = z * 32; hh < z * 32 + 32; hh++) {
        float w = W[(size_t)(s * 1024 + hh) * 1024 + c];
#pragma unroll
        for (int b = 0; b < 4; b++)
            acc[b] += img[(size_t)b * 1024 + hh] * w;
    }
    __shared__ float red[4][4][64];
#pragma unroll
    for (int b = 0; b < 4; b++) red[s][b][lane] = acc[b];
    __syncthreads();
    if (s == 0) {
#pragma unroll
        for (int b = 0; b < 4; b++)
            g_PI[z][(size_t)b * 1024 + c] =
                red[0][b][lane] + red[1][b][lane] + red[2][b][lane] + red[3][b][lane];
    }
}

__global__ void k_hir() {                           // grid 4 x 1024
    int b = blockIdx.x, c = threadIdx.x;
    float v = 0.f;
#pragma unroll
    for (int z = 0; z < 32; z++) v += g_PI[z][(size_t)b * 1024 + c];
    g_hImg[(size_t)b * 1024 + c] = v;
}

// ---------------- h[i,c4] = sum_z P[z][i%128, c4] + hImg[i/128, c4] ----------
__global__ void k_hassm() {                         // grid 512 x 256 (1 float4/thread)
    int i = blockIdx.x;
    int mi = i & 127, b = i >> 7;
    int c4 = threadIdx.x;                           // float4 index 0..255
    float4 v = *(const float4*)&g_hImg[(size_t)b * 1024 + c4 * 4];
#pragma unroll
    for (int z = 0; z < ZHX; z++) {
        float4 p = *(const float4*)&g_P[z][(size_t)mi * 1024 + c4 * 4];
        v.x += p.x; v.y += p.y; v.z += p.z; v.w += p.w;
    }
    *(float4*)&g_h[(size_t)i * 1024 + c4 * 4] = v;
}

// ---------------- scatter (last-edge-wins, deterministic, two-pass) ----------
__global__ void k_sc1(const int* __restrict__ er, const int* __restrict__ ec) {
    int idx = blockIdx.x * 256 + threadIdx.x;       // 64 x 256 = 16384
    atomicMax(&g_win[er[idx] * NN + ec[idx]], idx);
}

__global__ void k_sc2(const int* __restrict__ er, const int* __restrict__ ec,
                      const float* __restrict__ av) {
    int idx = blockIdx.x * 256 + threadIdx.x;
    int r = er[idx], c = ec[idx];
    int cell = r * NN + c;
    if (g_win[cell] == idx) {
        float ev = g_ha1[r] + g_ha2[c];
        g_e[cell]   = (ev >= 0.f) ? ev : 0.2f * ev;
        g_adj[cell] = av[idx] * 2.0f;
    }
}

// ---------------- adj dense min/max (two-stage) ------------------------------
__global__ void k_adjmm() {                         // grid 128 x 256
    int t = threadIdx.x;
    float mn = INFINITY, mx = -INFINITY;
    for (int i = blockIdx.x * 256 + t; i < CELLS; i += 128 * 256) {
        float v = g_adj[i];
        mn = fminf(mn, v); mx = fmaxf(mx, v);
    }
    __shared__ float smn[256], smx[256];
    smn[t] = mn; smx[t] = mx;
    __syncthreads();
    for (int off = 128; off > 0; off >>= 1) {
        if (t < off) {
            smn[t] = fminf(smn[t], smn[t + off]);
            smx[t] = fmaxf(smx[t], smx[t + off]);
        }
        __syncthreads();
    }
    if (t == 0) { g_mn[blockIdx.x] = smn[0]; g_mx[blockIdx.x] = smx[0]; }
}

__global__ void k_adjmmf() {                        // 1 block x 128
    int t = threadIdx.x;
    __shared__ float smn[128], smx[128];
    smn[t] = g_mn[t]; smx[t] = g_mx[t];
    __syncthreads();
    for (int off = 64; off > 0; off >>= 1) {
        if (t < off) {
            smn[t] = fminf(smn[t], smn[t + off]);
            smx[t] = fmaxf(smx[t], smx[t + off]);
        }
        __syncthreads();
    }
    if (t == 0) { g_amin_f = smn[0]; g_amax_f = smx[0]; }
}

// ---------------- row softmax + new_adj output -------------------------------
__global__ void k_softmax(float* __restrict__ out) {
    int r = blockIdx.x, t = threadIdx.x;            // 512 blocks x 512 threads
    float amin = g_amin_f;
    float inv  = 1.0f / (g_amax_f - amin);
    float v = g_e[r * NN + t];
    __shared__ float sh[512];
    sh[t] = v;
    __syncthreads();
    for (int off = 256; off > 0; off >>= 1) {
        if (t < off) sh[t] = fmaxf(sh[t], sh[t + off]);
        __syncthreads();
    }
    float m = sh[0];
    __syncthreads();
    float ev = expf(v - m);
    sh[t] = ev;
    __syncthreads();
    for (int off = 256; off > 0; off >>= 1) {
        if (t < off) sh[t] += sh[t + off];
        __syncthreads();
    }
    float att = ev / sh[0];
    g_att[r * NN + t] = att;
    out[r * NN + t] = att * (g_adj[r * NN + t] - amin) * inv;
}

// ---------------- hp partials: smem att tile + float4 h loads ----------------
__global__ void __launch_bounds__(256) k_hp() {
    __shared__ float As[8][128];
    int t = threadIdx.x;
    int r0 = blockIdx.x * 8;
    int z  = blockIdx.y;
    int k0 = z * 128;

    {   // att tile: rows r0..r0+7, k k0..k0+127
        int i = t >> 5, f4 = t & 31;
        float4 av = *(const float4*)(g_att + (size_t)(r0 + i) * NN + k0 + f4 * 4);
        *(float4*)&As[i][f4 * 4] = av;
    }
    __syncthreads();

    const float* Hb = g_h + (size_t)k0 * 1024 + t * 4;
    float acc[8][4];
#pragma unroll
    for (int i = 0; i < 8; i++)
#pragma unroll
        for (int j = 0; j < 4; j++) acc[i][j] = 0.f;

    for (int k = 0; k < 128; k += 4) {
        float4 h0 = *(const float4*)(Hb + (size_t)(k + 0) * 1024);
        float4 h1 = *(const float4*)(Hb + (size_t)(k + 1) * 1024);
        float4 h2 = *(const float4*)(Hb + (size_t)(k + 2) * 1024);
        float4 h3 = *(const float4*)(Hb + (size_t)(k + 3) * 1024);
#pragma unroll
        for (int i = 0; i < 8; i++) {
            float4 a = *(const float4*)&As[i][k];
            acc[i][0] += a.x * h0.x + a.y * h1.x + a.z * h2.x + a.w * h3.x;
            acc[i][1] += a.x * h0.y + a.y * h1.y + a.z * h2.y + a.w * h3.y;
            acc[i][2] += a.x * h0.z + a.y * h1.z + a.z * h2.z + a.w * h3.z;
            acc[i][3] += a.x * h0.w + a.y * h1.w + a.z * h2.w + a.w * h3.w;
        }
    }
#pragma unroll
    for (int i = 0; i < 8; i++)
        *(float4*)&g_Q[z][(size_t)(r0 + i) * 1024 + t * 4] =
            make_float4(acc[i][0], acc[i][1], acc[i][2], acc[i][3]);
}

// ---------------- hp reduce: hp = sum_z Q[z] (1 float4/thread) ---------------
__global__ void k_hpr() {                           // grid 512 x 256
    size_t idx = ((size_t)blockIdx.x * 256 + threadIdx.x) * 4;
    float4 a = *(const float4*)&g_Q[0][idx];
    float4 b = *(const float4*)&g_Q[1][idx];
    float4 c = *(const float4*)&g_Q[2][idx];
    float4 d = *(const float4*)&g_Q[3][idx];
    *(float4*)&g_hp[idx] = make_float4(a.x + b.x + c.x + d.x,
                                       a.y + b.y + c.y + d.y,
                                       a.z + b.z + c.z + d.z,
                                       a.w + b.w + c.w + d.w);
}

// ---------------- out1: 8 rows/block, hp chunk staged in smem ----------------
__global__ void __launch_bounds__(256) k_out1(const float* __restrict__ lw) {
    __shared__ float hs[OCHUNK];                    // 32 KB
    __shared__ float wsum[8][8];                    // [row][warp]
    int s = blockIdx.x;
    int r0 = blockIdx.y * 8;
    int t = threadIdx.x;
    int j0 = s * OCHUNK;

#pragma unroll
    for (int i = 0; i < OCHUNK / 1024; i++) {       // 8 float4 per thread
        int f4 = i * 256 + t;
        *(float4*)&hs[f4 * 4] = *(const float4*)(g_hp + j0 + f4 * 4);
    }
    __syncthreads();

    int warp = t >> 5, lane = t & 31;
#pragma unroll
    for (int r = 0; r < 8; r++) {
        int row = r0 + r;
        float acc = 0.f;
        if (row < 513) {
            const float4* wp = (const float4*)(lw + (size_t)row * LINK + j0);
#pragma unroll
            for (int i = 0; i < OCHUNK / 1024; i++) {
                int f4 = i * 256 + t;
                float4 w = wp[f4];
                float4 h = *(const float4*)&hs[f4 * 4];
                acc += w.x * h.x + w.y * h.y + w.z * h.z + w.w * h.w;
            }
        }
#pragma unroll
        for (int o = 16; o > 0; o >>= 1)
            acc += __shfl_down_sync(0xffffffffu, acc, o);
        if (lane == 0) wsum[r][warp] = acc;
    }
    __syncthreads();
    if (t < 8) {
        int row = r0 + t;
        if (row < 513) {
            float v = 0.f;
#pragma unroll
            for (int w2 = 0; w2 < 8; w2++) v += wsum[t][w2];
            g_part[s * 513 + row] = v;
        }
    }
}

// ---------------- normalize out1 (single block) ------------------------------
__global__ void k_norm(const float* __restrict__ lb, float* __restrict__ out) {
    int t = threadIdx.x;                            // 1024 threads
    bool valid = t < 513;
    float val = 0.f;
    if (valid) {
        float sum = lb[t];
        for (int s = 0; s < OSPLIT; s++) sum += g_part[s * 513 + t];
        val = sum;
    }
    __shared__ float smn[1024], smx[1024];
    smn[t] = valid ? val : INFINITY;
    smx[t] = valid ? val : -INFINITY;
    __syncthreads();
    for (int off = 512; off > 0; off >>= 1) {
        if (t < off) {
            smn[t] = fminf(smn[t], smn[t + off]);
            smx[t] = fmaxf(smx[t], smx[t + off]);
        }
        __syncthreads();
    }
    float mn = smn[0], mx = smx[0];
    float den = mx - mn;
    if (valid)
        out[CELLS + t] = (den == 0.f) ? 0.5f : (val - mn) / den;
}

// ---------------- launch ------------------------------------------------------
static int find_size(const int* s, int n, int sz, int occ) {
    int c = 0;
    for (int i = 0; i < n; i++)
        if (s[i] == sz) { if (c == occ) return i; c++; }
    return -1;
}

static cudaStream_t g_s1 = 0;
static cudaEvent_t  g_evF = 0, g_evS = 0;

extern "C" void kernel_launch(void* const* d_in, const int* in_sizes, int n_in,
                              void* d_out, int out_size) {
    int i_img = find_size(in_sizes, n_in, 4096, 0);
    int i_er  = find_size(in_sizes, n_in, 16384, 0);
    int i_ec  = find_size(in_sizes, n_in, 16384, 1);
    int i_av  = find_size(in_sizes, n_in, 16384, 2);
    int i_X   = find_size(in_sizes, n_in, 524288, 0);
    int i_W   = find_size(in_sizes, n_in, 4194304, 0);
    int i_a   = find_size(in_sizes, n_in, 2048, 0);
    int i_lw  = find_size(in_sizes, n_in, 268959744, 0);
    int i_lb  = find_size(in_sizes, n_in, 513, 0);
    if (i_img < 0 || i_er < 0 || i_ec < 0 || i_av < 0 || i_X < 0 ||
        i_W < 0 || i_a < 0 || i_lw < 0 || i_lb < 0) {
        i_img = 0; i_er = 1; i_ec = 2; i_av = 3; i_X = 4;
        i_W = 5; i_a = 6; i_lw = 7; i_lb = 8;
    }
    const float* img  = (const float*)d_in[i_img];
    const int*   erow = (const int*)d_in[i_er];
    const int*   ecol = (const int*)d_in[i_ec];
    const float* adjv = (const float*)d_in[i_av];
    const float* X    = (const float*)d_in[i_X];
    const float* W    = (const float*)d_in[i_W];
    const float* a    = (const float*)d_in[i_a];
    const float* lw   = (const float*)d_in[i_lw];
    const float* lb   = (const float*)d_in[i_lb];
    float* out = (float*)d_out;

    if (!g_s1) {  // resource setup on first (non-captured correctness) call
        cudaStreamCreateWithFlags(&g_s1, cudaStreamNonBlocking);
        cudaEventCreateWithFlags(&g_evF, cudaEventDisableTiming);
        cudaEventCreateWithFlags(&g_evS, cudaEventDisableTiming);
    }

    // fork: attention + img branch on side stream, core GEMM on main stream
    cudaEventRecord(g_evF, 0);
    cudaStreamWaitEvent(g_s1, g_evF, 0);

    // ---- side stream: e/attention path + img contribution ----
    k_zero<<<256, 1024, 0, g_s1>>>();
    k_wa<<<4096, 128, 0, g_s1>>>(W, a);
    k_havec<<<512, 256, 0, g_s1>>>(X, img);
    k_sc1<<<64, 256, 0, g_s1>>>(erow, ecol);
    k_sc2<<<64, 256, 0, g_s1>>>(erow, ecol, adjv);
    k_adjmm<<<128, 256, 0, g_s1>>>();
    k_adjmmf<<<1, 128, 0, g_s1>>>();
    k_softmax<<<512, 512, 0, g_s1>>>(out);
    k_himg<<<dim3(16, 32), 256, 0, g_s1>>>(img, W);
    k_hir<<<4, 1024, 0, g_s1>>>();
    cudaEventRecord(g_evS, g_s1);

    // ---- main stream: core GEMM partials ----
    k_hx<<<dim3(16, ZHX), 256>>>(X, W);

    // join: need g_hImg (side) for hassm, g_att (side) for hp
    cudaStreamWaitEvent(0, g_evS, 0);
    k_hassm<<<512, 256>>>();
    k_hp<<<dim3(64, 4), 256>>>();
    k_hpr<<<512, 256>>>();
    k_out1<<<dim3(OSPLIT, 65), 256>>>(lw);
    k_norm<<<1, 1024>>>(lb, out);
}

// round 16
// speedup vs baseline: 1.1515x; 1.1515x over previous
#include <cuda_runtime.h>
#include <math.h>

#define NN    512
#define HH    1024
#define EE    16384
#define LINK  (NN*HH)     // 524288
#define CELLS (NN*NN)     // 262144
#define OSPLIT 64
#define OCHUNK (LINK/OSPLIT)   // 8192 floats = 32 KB
#define ZHX   32               // k_hx split-K chunks

// ---------------- scratch (device globals; no allocation allowed) -------------
__device__ __align__(16) float g_P[ZHX][128*1024]; // k_hx split-K partials (16 MB)
__device__ __align__(16) float g_Q[4][LINK];       // k_hp split-K partials (8 MB)
__device__ __align__(16) float g_PI[32][4*1024];   // k_himg split-K partials
__device__ __align__(16) float g_h[LINK];          // h (512x1024)
__device__ __align__(16) float g_Wa1[4096];        // W @ a[0:1024]
__device__ __align__(16) float g_Wa2[4096];        // W @ a[1024:2048]
__device__ float g_ha1[NN];
__device__ float g_ha2[NN];
__device__ int   g_win[CELLS];
__device__ __align__(16) float g_e[CELLS];
__device__ __align__(16) float g_adj[CELLS];
__device__ __align__(16) float g_att[CELLS];
__device__ __align__(16) float g_hp[LINK];         // h_prime (512x1024)
__device__ float g_part[OSPLIT*513];
__device__ float g_mn[128], g_mx[128];

// ---------------- fused zero + Wa ---------------------------------------------
// blocks [0,4096): Wa row j ; blocks [4096,5120): zero 256 cells each
__global__ void k_zwa(const float* __restrict__ W, const float* __restrict__ a) {
    int t = threadIdx.x;                            // 256 threads
    if (blockIdx.x >= 4096) {
        int i = (blockIdx.x - 4096) * 256 + t;      // 1024 blocks -> 262144
        g_win[i] = -1;
        g_e[i]   = 0.0f;
        g_adj[i] = 0.0f;
        return;
    }
    int j = blockIdx.x;
    float s1 = 0.f, s2 = 0.f;
    for (int c = t; c < 1024; c += 256) {
        float w = W[(size_t)j * 1024 + c];
        s1 += w * a[c];
        s2 += w * a[1024 + c];
    }
    __shared__ float r1[256], r2[256];
    r1[t] = s1; r2[t] = s2;
    __syncthreads();
    for (int off = 128; off > 0; off >>= 1) {
        if (t < off) { r1[t] += r1[t + off]; r2[t] += r2[t + off]; }
        __syncthreads();
    }
    if (t == 0) { g_Wa1[j] = r1[0]; g_Wa2[j] = r2[0]; }
}

// ---------------- ha1[i] = sum_j fx[i,j] Wa1[j] (fx computed inline) ----------
__global__ void k_havec(const float* __restrict__ X, const float* __restrict__ img) {
    int i = blockIdx.x;                            // 512 blocks x 256 threads
    int t = threadIdx.x;
    int base_n = 4 * (i & 127);
    int b = i >> 7;
    float s1 = 0.f, s2 = 0.f;
    for (int j = t; j < 4096; j += 256) {
        int hh = j & 1023;
        float fx = X[(size_t)(base_n + (j >> 10)) * 1024 + hh]
                 + img[(size_t)b * 1024 + hh];
        s1 += fx * g_Wa1[j];
        s2 += fx * g_Wa2[j];
    }
    __shared__ float r1[256], r2[256];
    r1[t] = s1; r2[t] = s2;
    __syncthreads();
    for (int off = 128; off > 0; off >>= 1) {
        if (t < off) { r1[t] += r1[t + off]; r2[t] += r2[t + off]; }
        __syncthreads();
    }
    if (t == 0) { g_ha1[i] = r1[0]; g_ha2[i] = r2[0]; }
}

// ---------------- core GEMM: smem X tile + float4 W loads --------------------
// z in [0,32): q = z>>3, hh0 = (z&7)*128. grid (16 m-groups, 32 z), 256 thr.
__global__ void __launch_bounds__(256, 3) k_hx(const float* __restrict__ X,
                                               const float* __restrict__ W) {
    __shared__ float Xs[8][128];
    int t = threadIdx.x;
    int m0 = blockIdx.x * 8;
    int z  = blockIdx.y;
    int q = z >> 3, hh0 = (z & 7) * 128;

    {   // cooperative X tile load: rows 4*(m0+i)+q, cols hh0..hh0+127
        int i = t >> 5, f4 = t & 31;
        float4 xv = *(const float4*)(X + (size_t)(4 * (m0 + i) + q) * 1024 + hh0 + f4 * 4);
        *(float4*)&Xs[i][f4 * 4] = xv;
    }
    __syncthreads();

    const float* Wb = W + (size_t)(q * 1024 + hh0) * 1024 + t * 4;
    float acc[8][4];
#pragma unroll
    for (int i = 0; i < 8; i++)
#pragma unroll
        for (int j = 0; j < 4; j++) acc[i][j] = 0.f;

    for (int hh = 0; hh < 128; hh += 4) {
        float4 w0 = *(const float4*)(Wb + (size_t)(hh + 0) * 1024);
        float4 w1 = *(const float4*)(Wb + (size_t)(hh + 1) * 1024);
        float4 w2 = *(const float4*)(Wb + (size_t)(hh + 2) * 1024);
        float4 w3 = *(const float4*)(Wb + (size_t)(hh + 3) * 1024);
#pragma unroll
        for (int i = 0; i < 8; i++) {
            float4 x = *(const float4*)&Xs[i][hh];
            acc[i][0] += x.x * w0.x + x.y * w1.x + x.z * w2.x + x.w * w3.x;
            acc[i][1] += x.x * w0.y + x.y * w1.y + x.z * w2.y + x.w * w3.y;
            acc[i][2] += x.x * w0.z + x.y * w1.z + x.z * w2.z + x.w * w3.z;
            acc[i][3] += x.x * w0.w + x.y * w1.w + x.z * w2.w + x.w * w3.w;
        }
    }
#pragma unroll
    for (int i = 0; i < 8; i++)
        *(float4*)&g_P[z][(size_t)(m0 + i) * 1024 + t * 4] =
            make_float4(acc[i][0], acc[i][1], acc[i][2], acc[i][3]);
}

// ---------------- img @ W (grid 16 x 32) -------------------------------------
__global__ void k_himg(const float* __restrict__ img, const float* __restrict__ W) {
    int t = threadIdx.x;
    int lane = t & 63, s = t >> 6;
    int c = blockIdx.x * 64 + lane;
    int z = blockIdx.y;                             // 32 chunks of 32 hh
    float acc[4] = {0.f,0.f,0.f,0.f};
    for (int hh = z * 32; hh < z * 32 + 32; hh++) {
        float w = W[(size_t)(s * 1024 + hh) * 1024 + c];
#pragma unroll
        for (int b = 0; b < 4; b++)
            acc[b] += img[(size_t)b * 1024 + hh] * w;
    }
    __shared__ float red[4][4][64];
#pragma unroll
    for (int b = 0; b < 4; b++) red[s][b][lane] = acc[b];
    __syncthreads();
    if (s == 0) {
#pragma unroll
        for (int b = 0; b < 4; b++)
            g_PI[z][(size_t)b * 1024 + c] =
                red[0][b][lane] + red[1][b][lane] + red[2][b][lane] + red[3][b][lane];
    }
}

// ---------------- h = sum_z P[z] + sum_z PI[z] (k_hir folded in) -------------
__global__ void k_hassm() {                         // grid 512 x 256 (1 float4/thread)
    int i = blockIdx.x;
    int mi = i & 127, b = i >> 7;
    int c4 = threadIdx.x;                           // float4 index 0..255
    float4 v = make_float4(0.f, 0.f, 0.f, 0.f);
#pragma unroll
    for (int z = 0; z < 32; z++) {
        float4 pi = *(const float4*)&g_PI[z][(size_t)b * 1024 + c4 * 4];
        v.x += pi.x; v.y += pi.y; v.z += pi.z; v.w += pi.w;
    }
#pragma unroll
    for (int z = 0; z < ZHX; z++) {
        float4 p = *(const float4*)&g_P[z][(size_t)mi * 1024 + c4 * 4];
        v.x += p.x; v.y += p.y; v.z += p.z; v.w += p.w;
    }
    *(float4*)&g_h[(size_t)i * 1024 + c4 * 4] = v;
}

// ---------------- scatter (last-edge-wins, deterministic, two-pass) ----------
__global__ void k_sc1(const int* __restrict__ er, const int* __restrict__ ec) {
    int idx = blockIdx.x * 256 + threadIdx.x;       // 64 x 256 = 16384
    atomicMax(&g_win[er[idx] * NN + ec[idx]], idx);
}

__global__ void k_sc2(const int* __restrict__ er, const int* __restrict__ ec,
                      const float* __restrict__ av) {
    int idx = blockIdx.x * 256 + threadIdx.x;
    int r = er[idx], c = ec[idx];
    int cell = r * NN + c;
    if (g_win[cell] == idx) {
        float ev = g_ha1[r] + g_ha2[c];
        g_e[cell]   = (ev >= 0.f) ? ev : 0.2f * ev;
        g_adj[cell] = av[idx] * 2.0f;
    }
}

// ---------------- adj dense min/max (stage 1 only) ---------------------------
__global__ void k_adjmm() {                         // grid 128 x 256
    int t = threadIdx.x;
    float mn = INFINITY, mx = -INFINITY;
    for (int i = blockIdx.x * 256 + t; i < CELLS; i += 128 * 256) {
        float v = g_adj[i];
        mn = fminf(mn, v); mx = fmaxf(mx, v);
    }
    __shared__ float smn[256], smx[256];
    smn[t] = mn; smx[t] = mx;
    __syncthreads();
    for (int off = 128; off > 0; off >>= 1) {
        if (t < off) {
            smn[t] = fminf(smn[t], smn[t + off]);
            smx[t] = fmaxf(smx[t], smx[t + off]);
        }
        __syncthreads();
    }
    if (t == 0) { g_mn[blockIdx.x] = smn[0]; g_mx[blockIdx.x] = smx[0]; }
}

// ---------------- row softmax + new_adj output (adjmm stage-2 folded in) -----
__global__ void k_softmax(float* __restrict__ out) {
    int r = blockIdx.x, t = threadIdx.x;            // 512 blocks x 512 threads
    __shared__ float smm[256];
    // reduce the 128 per-block min/max partials locally (free vs extra launch)
    if (t < 128) smm[t] = g_mn[t];
    else if (t < 256) smm[t] = g_mx[t - 128];
    __syncthreads();
    for (int off = 64; off > 0; off >>= 1) {
        if (t < off) smm[t] = fminf(smm[t], smm[t + off]);
        else if (t >= 128 && t < 128 + off) smm[t] = fmaxf(smm[t], smm[t + off]);
        __syncthreads();
    }
    float amin = smm[0];
    float inv  = 1.0f / (smm[128] - amin);
    __syncthreads();

    float v = g_e[r * NN + t];
    __shared__ float sh[512];
    sh[t] = v;
    __syncthreads();
    for (int off = 256; off > 0; off >>= 1) {
        if (t < off) sh[t] = fmaxf(sh[t], sh[t + off]);
        __syncthreads();
    }
    float m = sh[0];
    __syncthreads();
    float ev = expf(v - m);
    sh[t] = ev;
    __syncthreads();
    for (int off = 256; off > 0; off >>= 1) {
        if (t < off) sh[t] += sh[t + off];
        __syncthreads();
    }
    float att = ev / sh[0];
    g_att[r * NN + t] = att;
    out[r * NN + t] = att * (g_adj[r * NN + t] - amin) * inv;
}

// ---------------- hp partials: smem att tile + float4 h loads ----------------
__global__ void __launch_bounds__(256) k_hp() {
    __shared__ float As[8][128];
    int t = threadIdx.x;
    int r0 = blockIdx.x * 8;
    int z  = blockIdx.y;
    int k0 = z * 128;

    {   // att tile: rows r0..r0+7, k k0..k0+127
        int i = t >> 5, f4 = t & 31;
        float4 av = *(const float4*)(g_att + (size_t)(r0 + i) * NN + k0 + f4 * 4);
        *(float4*)&As[i][f4 * 4] = av;
    }
    __syncthreads();

    const float* Hb = g_h + (size_t)k0 * 1024 + t * 4;
    float acc[8][4];
#pragma unroll
    for (int i = 0; i < 8; i++)
#pragma unroll
        for (int j = 0; j < 4; j++) acc[i][j] = 0.f;

    for (int k = 0; k < 128; k += 4) {
        float4 h0 = *(const float4*)(Hb + (size_t)(k + 0) * 1024);
        float4 h1 = *(const float4*)(Hb + (size_t)(k + 1) * 1024);
        float4 h2 = *(const float4*)(Hb + (size_t)(k + 2) * 1024);
        float4 h3 = *(const float4*)(Hb + (size_t)(k + 3) * 1024);
#pragma unroll
        for (int i = 0; i < 8; i++) {
            float4 a = *(const float4*)&As[i][k];
            acc[i][0] += a.x * h0.x + a.y * h1.x + a.z * h2.x + a.w * h3.x;
            acc[i][1] += a.x * h0.y + a.y * h1.y + a.z * h2.y + a.w * h3.y;
            acc[i][2] += a.x * h0.z + a.y * h1.z + a.z * h2.z + a.w * h3.z;
            acc[i][3] += a.x * h0.w + a.y * h1.w + a.z * h2.w + a.w * h3.w;
        }
    }
#pragma unroll
    for (int i = 0; i < 8; i++)
        *(float4*)&g_Q[z][(size_t)(r0 + i) * 1024 + t * 4] =
            make_float4(acc[i][0], acc[i][1], acc[i][2], acc[i][3]);
}

// ---------------- hp reduce: hp = sum_z Q[z] (1 float4/thread) ---------------
__global__ void k_hpr() {                           // grid 512 x 256
    size_t idx = ((size_t)blockIdx.x * 256 + threadIdx.x) * 4;
    float4 a = *(const float4*)&g_Q[0][idx];
    float4 b = *(const float4*)&g_Q[1][idx];
    float4 c = *(const float4*)&g_Q[2][idx];
    float4 d = *(const float4*)&g_Q[3][idx];
    *(float4*)&g_hp[idx] = make_float4(a.x + b.x + c.x + d.x,
                                       a.y + b.y + c.y + d.y,
                                       a.z + b.z + c.z + d.z,
                                       a.w + b.w + c.w + d.w);
}

// ---------------- out1: 8 rows/block, hp chunk staged in smem ----------------
__global__ void __launch_bounds__(256) k_out1(const float* __restrict__ lw) {
    __shared__ float hs[OCHUNK];                    // 32 KB
    __shared__ float wsum[8][8];                    // [row][warp]
    int s = blockIdx.x;
    int r0 = blockIdx.y * 8;
    int t = threadIdx.x;
    int j0 = s * OCHUNK;

#pragma unroll
    for (int i = 0; i < OCHUNK / 1024; i++) {       // 8 float4 per thread
        int f4 = i * 256 + t;
        *(float4*)&hs[f4 * 4] = *(const float4*)(g_hp + j0 + f4 * 4);
    }
    __syncthreads();

    int warp = t >> 5, lane = t & 31;
#pragma unroll
    for (int r = 0; r < 8; r++) {
        int row = r0 + r;
        float acc = 0.f;
        if (row < 513) {
            const float4* wp = (const float4*)(lw + (size_t)row * LINK + j0);
#pragma unroll
            for (int i = 0; i < OCHUNK / 1024; i++) {
                int f4 = i * 256 + t;
                float4 w = wp[f4];
                float4 h = *(const float4*)&hs[f4 * 4];
                acc += w.x * h.x + w.y * h.y + w.z * h.z + w.w * h.w;
            }
        }
#pragma unroll
        for (int o = 16; o > 0; o >>= 1)
            acc += __shfl_down_sync(0xffffffffu, acc, o);
        if (lane == 0) wsum[r][warp] = acc;
    }
    __syncthreads();
    if (t < 8) {
        int row = r0 + t;
        if (row < 513) {
            float v = 0.f;
#pragma unroll
            for (int w2 = 0; w2 < 8; w2++) v += wsum[t][w2];
            g_part[s * 513 + row] = v;
        }
    }
}

// ---------------- normalize out1 (single block) ------------------------------
__global__ void k_norm(const float* __restrict__ lb, float* __restrict__ out) {
    int t = threadIdx.x;                            // 1024 threads
    bool valid = t < 513;
    float val = 0.f;
    if (valid) {
        float sum = lb[t];
        for (int s = 0; s < OSPLIT; s++) sum += g_part[s * 513 + t];
        val = sum;
    }
    __shared__ float smn[1024], smx[1024];
    smn[t] = valid ? val : INFINITY;
    smx[t] = valid ? val : -INFINITY;
    __syncthreads();
    for (int off = 512; off > 0; off >>= 1) {
        if (t < off) {
            smn[t] = fminf(smn[t], smn[t + off]);
            smx[t] = fmaxf(smx[t], smx[t + off]);
        }
        __syncthreads();
    }
    float mn = smn[0], mx = smx[0];
    float den = mx - mn;
    if (valid)
        out[CELLS + t] = (den == 0.f) ? 0.5f : (val - mn) / den;
}

// ---------------- launch ------------------------------------------------------
static int find_size(const int* s, int n, int sz, int occ) {
    int c = 0;
    for (int i = 0; i < n; i++)
        if (s[i] == sz) { if (c == occ) return i; c++; }
    return -1;
}

extern "C" void kernel_launch(void* const* d_in, const int* in_sizes, int n_in,
                              void* d_out, int out_size) {
    int i_img = find_size(in_sizes, n_in, 4096, 0);
    int i_er  = find_size(in_sizes, n_in, 16384, 0);
    int i_ec  = find_size(in_sizes, n_in, 16384, 1);
    int i_av  = find_size(in_sizes, n_in, 16384, 2);
    int i_X   = find_size(in_sizes, n_in, 524288, 0);
    int i_W   = find_size(in_sizes, n_in, 4194304, 0);
    int i_a   = find_size(in_sizes, n_in, 2048, 0);
    int i_lw  = find_size(in_sizes, n_in, 268959744, 0);
    int i_lb  = find_size(in_sizes, n_in, 513, 0);
    if (i_img < 0 || i_er < 0 || i_ec < 0 || i_av < 0 || i_X < 0 ||
        i_W < 0 || i_a < 0 || i_lw < 0 || i_lb < 0) {
        i_img = 0; i_er = 1; i_ec = 2; i_av = 3; i_X = 4;
        i_W = 5; i_a = 6; i_lw = 7; i_lb = 8;
    }
    const float* img  = (const float*)d_in[i_img];
    const int*   erow = (const int*)d_in[i_er];
    const int*   ecol = (const int*)d_in[i_ec];
    const float* adjv = (const float*)d_in[i_av];
    const float* X    = (const float*)d_in[i_X];
    const float* W    = (const float*)d_in[i_W];
    const float* a    = (const float*)d_in[i_a];
    const float* lw   = (const float*)d_in[i_lw];
    const float* lb   = (const float*)d_in[i_lb];
    float* out = (float*)d_out;

    k_zwa<<<5120, 256>>>(W, a);                     // zero + Wa fused
    k_havec<<<512, 256>>>(X, img);
    k_hx<<<dim3(16, ZHX), 256>>>(X, W);
    k_himg<<<dim3(16, 32), 256>>>(img, W);
    k_hassm<<<512, 256>>>();                        // hir folded in
    k_sc1<<<64, 256>>>(erow, ecol);
    k_sc2<<<64, 256>>>(erow, ecol, adjv);
    k_adjmm<<<128, 256>>>();
    k_softmax<<<512, 512>>>(out);                   // adjmmf folded in
    k_hp<<<dim3(64, 4), 256>>>();
    k_hpr<<<512, 256>>>();
    k_out1<<<dim3(OSPLIT, 65), 256>>>(lw);
    k_norm<<<1, 1024>>>(lb, out);
}